// round 9
// baseline (speedup 1.0000x reference)
#include <cuda_runtime.h>
#include <cuda_bf16.h>
#include <math.h>

#define CROP 448
#define NR   56      // cells per side
#define NB   55      // blocks per side
#define B    48
#define IMG  512
#define TOP  32
#define QPR  112     // float4 quads per row (448/4)
#define SGW  456     // padded smem row width: col c at index c+4

// Cell histogram scratch: [b][cell_r][cell_c][bin]
__device__ float g_hist[(size_t)B * NR * NR * 9];

__device__ __forceinline__ float fsqrt_approx(float x) {
    float r;
    asm("sqrt.approx.f32 %0, %1;" : "=f"(r) : "f"(x));
    return r;
}

// ---------------------------------------------------------------------------
// Kernel 1: gray -> sqrt -> gradients -> per-cell prefix histograms
// grid: (NR, B), block: 448 threads (one per crop column)   [R7 structure]
// ---------------------------------------------------------------------------
__global__ __launch_bounds__(CROP) void hog_cells_kernel(
    const float* __restrict__ x, const float* __restrict__ coeffs,
    float* __restrict__ hist)
{
    __shared__ float sg[10][SGW];

    const int cr = blockIdx.x;       // cell row 0..55
    const int b  = blockIdx.y;
    const int c  = threadIdx.x;      // crop column 0..447
    const int r0 = cr * 8;

    const float c0 = coeffs[0], c1 = coeffs[1], c2 = coeffs[2];
    const float* base = x + (size_t)b * 3 * IMG * IMG;

    #pragma unroll
    for (int e = c; e < 10 * QPR; e += CROP) {
        int i = e / QPR;
        int q = e - i * QPR;
        int r = r0 - 1 + i;
        if (r < 0) r = -r;                        // -1 -> 1
        if (r > CROP - 1) r = 2 * (CROP - 1) - r; // 448 -> 446
        const float4* p = (const float4*)(base + (size_t)(r + TOP) * IMG + TOP) + q;
        float4 a0 = p[0];
        float4 a1 = p[(IMG * IMG) / 4];
        float4 a2 = p[(2 * IMG * IMG) / 4];
        float4 g;
        g.x = fsqrt_approx(fmaf(c0, a0.x, fmaf(c1, a1.x, c2 * a2.x)));
        g.y = fsqrt_approx(fmaf(c0, a0.y, fmaf(c1, a1.y, c2 * a2.y)));
        g.z = fsqrt_approx(fmaf(c0, a0.z, fmaf(c1, a1.z, c2 * a2.z)));
        g.w = fsqrt_approx(fmaf(c0, a0.w, fmaf(c1, a1.w, c2 * a2.w)));
        *((float4*)&sg[i][4 + q * 4]) = g;
    }
    __syncthreads();

    if (c < 20) {
        int i = c >> 1;
        if (c & 1) sg[i][452] = sg[i][450];   // col 448 := col 446
        else       sg[i][3]   = sg[i][5];     // col -1  := col 1
    }
    __syncthreads();

    const float SN[8] = {0.342020143f, 0.642787610f, 0.866025404f, 0.984807753f,
                         0.984807753f, 0.866025404f, 0.642787610f, 0.342020143f};
    const float CS[8] = {0.939692621f, 0.766044443f, 0.500000000f, 0.173648178f,
                        -0.173648178f,-0.500000000f,-0.766044443f,-0.939692621f};

    float vreg[10];
    #pragma unroll
    for (int i = 0; i < 10; i++) vreg[i] = sg[i][c + 4];

    float H[9];
    #pragma unroll
    for (int k = 0; k < 9; k++) H[k] = 0.f;

    #pragma unroll
    for (int i = 0; i < 8; i++) {
        float gr = vreg[i + 2] - vreg[i];
        float gc = sg[i + 1][c + 5] - sg[i + 1][c + 3];

        float mag = fsqrt_approx(fmaf(gr, gr, gc * gc));

        bool neg = (gr < 0.f) || (gr == 0.f && gc < 0.f);
        float u  = neg ? -gc : gc;
        float vv = neg ? -gr : gr;

        H[0] += mag;
        #pragma unroll
        for (int k = 0; k < 8; k++) {
            float t = fmaf(CS[k], vv, -SN[k] * u);
            if (t >= 0.f) H[k + 1] += mag;
        }
    }

    #pragma unroll
    for (int k = 0; k < 9; k++) {
        H[k] += __shfl_xor_sync(0xffffffffu, H[k], 1);
        H[k] += __shfl_xor_sync(0xffffffffu, H[k], 2);
        H[k] += __shfl_xor_sync(0xffffffffu, H[k], 4);
    }

    if ((c & 7) == 0) {
        int cell = c >> 3;
        size_t cidx = ((size_t)b * NR + cr) * NR + cell;
        #pragma unroll
        for (int k = 0; k < 9; k++) {
            float hk = ((k < 8) ? (H[k] - H[k + 1]) : H[8]) * (1.0f / 64.0f);
            hist[cidx * 9 + k] = hk;
        }
    }
}

// ---------------------------------------------------------------------------
// Kernel 2: L2-Hys block normalization — barrier-free, smem-free.
// 4 lanes per block descriptor: lane l of a warp handles cell g=l&3 of the
// (l>>2)-th of the warp's 8 consecutive blocks (flat over b,I,J). Hist reads
// hit L2 (written by k1); norms via intra-group shfl; direct STG.
// ---------------------------------------------------------------------------
#define K2_THREADS 256
#define NBLOCKS (B * NB * NB)   // 145200

__global__ __launch_bounds__(K2_THREADS) void hog_blocks_kernel(
    const float* __restrict__ hist, float* __restrict__ out)
{
    const int warp_g = (blockIdx.x * K2_THREADS + threadIdx.x) >> 5;
    const int lane   = threadIdx.x & 31;
    const int g      = lane & 3;         // cell within block
    const int m      = lane >> 2;        // which of this warp's 8 blocks

    int flat = warp_g * 8 + m;           // block descriptor id
    const bool valid = (flat < NBLOCKS);
    if (!valid) flat = NBLOCKS - 1;      // clamp: converged shuffles, safe reads

    const int J   = flat % NB;
    const int t   = flat / NB;
    const int I   = t % NB;
    const int b   = t / NB;

    // This lane's cell: row I + (g>>1), col J + (g&1).
    const float* cell =
        hist + (((size_t)b * NR + I + (g >> 1)) * NR + (J + (g & 1))) * 9;

    float v[9];
    float ss = 0.f;
    #pragma unroll
    for (int k = 0; k < 9; k++) {
        float f = cell[k];
        v[k] = f;
        ss = fmaf(f, f, ss);
    }
    // Sum over the 4 lanes of this block's group (xor 1,2 stay in-group).
    ss += __shfl_xor_sync(0xffffffffu, ss, 1);
    ss += __shfl_xor_sync(0xffffffffu, ss, 2);
    float inv1 = rsqrtf(ss + 1e-10f);

    float ss2 = 0.f;
    #pragma unroll
    for (int k = 0; k < 9; k++) {
        float f = fminf(v[k] * inv1, 0.2f);
        v[k] = f;
        ss2 = fmaf(f, f, ss2);
    }
    ss2 += __shfl_xor_sync(0xffffffffu, ss2, 1);
    ss2 += __shfl_xor_sync(0xffffffffu, ss2, 2);
    float inv2 = rsqrtf(ss2 + 1e-10f);

    if (valid) {
        float* o = out + (size_t)flat * 36 + g * 9;
        #pragma unroll
        for (int k = 0; k < 9; k++) o[k] = v[k] * inv2;
    }
}

// ---------------------------------------------------------------------------
extern "C" void kernel_launch(void* const* d_in, const int* in_sizes, int n_in,
                              void* d_out, int out_size)
{
    const float* x      = (const float*)d_in[0];
    const float* coeffs = (const float*)d_in[1];
    float* out          = (float*)d_out;

    float* hist;
    cudaGetSymbolAddress((void**)&hist, g_hist);

    dim3 g1(NR, B);
    hog_cells_kernel<<<g1, CROP>>>(x, coeffs, hist);

    // 145200 blocks, 8 per warp -> 18150 warps -> 2269 CTAs of 256 threads.
    const int nwarps = (NBLOCKS + 7) / 8;
    const int ncta   = (nwarps * 32 + K2_THREADS - 1) / K2_THREADS;
    hog_blocks_kernel<<<ncta, K2_THREADS>>>(hist, out);
}

// round 10
// speedup vs baseline: 1.2020x; 1.2020x over previous
#include <cuda_runtime.h>
#include <cuda_bf16.h>
#include <math.h>

#define CROP 448
#define NR   56      // cells per side
#define NB   55      // blocks per side
#define B    48
#define IMG  512
#define TOP  32
#define QPR  112     // float4 quads per row (448/4)
#define SGW  456     // padded smem row width: col c at index c+4

// Cell histogram scratch: [b][cell_r][cell_c][bin]
__device__ float g_hist[(size_t)B * NR * NR * 9];
// Per-cell sum of squares: [b][cell_r][cell_c]
__device__ float g_cellss[(size_t)B * NR * NR];

__device__ __forceinline__ float fsqrt_approx(float x) {
    float r;
    asm("sqrt.approx.f32 %0, %1;" : "=f"(r) : "f"(x));
    return r;
}

// ---------------------------------------------------------------------------
// Kernel 1: gray -> sqrt -> gradients -> per-cell prefix histograms (+cell ss)
// grid: (NR, B), block: 448 threads (one per crop column)
// min 3 CTAs/SM (48-reg cap) for latency hiding.
// ---------------------------------------------------------------------------
__global__ __launch_bounds__(CROP, 3) void hog_cells_kernel(
    const float* __restrict__ x, const float* __restrict__ coeffs,
    float* __restrict__ hist, float* __restrict__ cellss)
{
    __shared__ float sg[10][SGW];

    const int cr = blockIdx.x;       // cell row 0..55
    const int b  = blockIdx.y;
    const int c  = threadIdx.x;      // crop column 0..447
    const int r0 = cr * 8;

    const float c0 = coeffs[0], c1 = coeffs[1], c2 = coeffs[2];
    const float* base = x + (size_t)b * 3 * IMG * IMG;

    // Stage 10 rows of sqrt(gray); reflection clamp makes boundary gr = 0.
    // Edge-column reflections (col -1 := col 1, col 448 := col 446) are
    // written inline by the threads handling quads 0 and 111.
    #pragma unroll
    for (int e = c; e < 10 * QPR; e += CROP) {
        int i = e / QPR;
        int q = e - i * QPR;
        int r = r0 - 1 + i;
        if (r < 0) r = -r;                        // -1 -> 1
        if (r > CROP - 1) r = 2 * (CROP - 1) - r; // 448 -> 446
        const float4* p = (const float4*)(base + (size_t)(r + TOP) * IMG + TOP) + q;
        float4 a0 = p[0];
        float4 a1 = p[(IMG * IMG) / 4];
        float4 a2 = p[(2 * IMG * IMG) / 4];
        float4 g;
        g.x = fsqrt_approx(fmaf(c0, a0.x, fmaf(c1, a1.x, c2 * a2.x)));
        g.y = fsqrt_approx(fmaf(c0, a0.y, fmaf(c1, a1.y, c2 * a2.y)));
        g.z = fsqrt_approx(fmaf(c0, a0.z, fmaf(c1, a1.z, c2 * a2.z)));
        g.w = fsqrt_approx(fmaf(c0, a0.w, fmaf(c1, a1.w, c2 * a2.w)));
        *((float4*)&sg[i][4 + q * 4]) = g;
        if (q == 0)       sg[i][3]   = g.y;   // col -1  := col 1
        if (q == QPR - 1) sg[i][452] = g.z;   // col 448 := col 446
    }
    __syncthreads();

    const float SN[8] = {0.342020143f, 0.642787610f, 0.866025404f, 0.984807753f,
                         0.984807753f, 0.866025404f, 0.642787610f, 0.342020143f};
    const float CS[8] = {0.939692621f, 0.766044443f, 0.500000000f, 0.173648178f,
                        -0.173648178f,-0.500000000f,-0.766044443f,-0.939692621f};

    float vreg[10];
    #pragma unroll
    for (int i = 0; i < 10; i++) vreg[i] = sg[i][c + 4];

    // Prefix histogram: H[k] = sum of mag over pixels with angle >= 20k.
    float H[9];
    #pragma unroll
    for (int k = 0; k < 9; k++) H[k] = 0.f;

    #pragma unroll
    for (int i = 0; i < 8; i++) {
        float gr = vreg[i + 2] - vreg[i];
        float gc = sg[i + 1][c + 5] - sg[i + 1][c + 3];

        float mag = fsqrt_approx(fmaf(gr, gr, gc * gc));

        bool neg = (gr < 0.f) || (gr == 0.f && gc < 0.f);
        float u  = neg ? -gc : gc;
        float vv = neg ? -gr : gr;

        H[0] += mag;
        #pragma unroll
        for (int k = 0; k < 8; k++) {
            float t = fmaf(CS[k], vv, -SN[k] * u);
            if (t >= 0.f) H[k + 1] += mag;
        }
    }

    #pragma unroll
    for (int k = 0; k < 9; k++) {
        H[k] += __shfl_xor_sync(0xffffffffu, H[k], 1);
        H[k] += __shfl_xor_sync(0xffffffffu, H[k], 2);
        H[k] += __shfl_xor_sync(0xffffffffu, H[k], 4);
    }

    if ((c & 7) == 0) {
        int cell = c >> 3;
        size_t cidx = ((size_t)b * NR + cr) * NR + cell;
        float ss = 0.f;
        #pragma unroll
        for (int k = 0; k < 9; k++) {
            float hk = ((k < 8) ? (H[k] - H[k + 1]) : H[8]) * (1.0f / 64.0f);
            hist[cidx * 9 + k] = hk;
            ss += hk * hk;
        }
        cellss[cidx] = ss;
    }
}

// ---------------------------------------------------------------------------
// Kernel 2: L2-Hys block normalization. One CTA per (b, I) block-row.
// [R7 version verbatim — best measured 12.35us]
// ---------------------------------------------------------------------------
#define K2_THREADS 256
#define VSTRIDE 37          // padded per-block stride in vbuf (kills conflicts)

__global__ __launch_bounds__(K2_THREADS) void hog_blocks_kernel(
    const float* __restrict__ hist, const float* __restrict__ cellss,
    float* __restrict__ out)
{
    __shared__ float sh[2 * NR * 9];      // hist rows I, I+1 (1008)
    __shared__ float scs[2 * NR];         // cell ss rows I, I+1 (112)
    __shared__ float vbuf[NB * VSTRIDE];  // normalized blocks, padded stride

    const int b = blockIdx.x / NB;
    const int I = blockIdx.x % NB;
    const int tid = threadIdx.x;

    {
        const float4* src4 = (const float4*)(hist + ((size_t)b * NR + I) * NR * 9);
        if (tid < 252) ((float4*)sh)[tid] = src4[tid];
        const float* cs = cellss + ((size_t)b * NR + I) * NR;
        if (tid < 2 * NR) scs[tid] = cs[tid];
    }
    __syncthreads();

    const int w    = tid >> 5;
    const int lane = tid & 31;
    const int g    = lane & 3;            // cell within block
    const int J    = w + 8 * (lane >> 2); // block column (may be >= NB)
    const int Jc   = (J < NB) ? J : (NB - 1);  // clamped for safe reads

    float inv1 = rsqrtf(scs[Jc] + scs[Jc + 1] + scs[NR + Jc] + scs[NR + Jc + 1]
                        + 1e-10f);

    const float* cell = sh + (g >> 1) * (NR * 9) + (Jc + (g & 1)) * 9;
    float v[9];
    float ss = 0.f;
    #pragma unroll
    for (int k = 0; k < 9; k++) {
        float f = fminf(cell[k] * inv1, 0.2f);
        v[k] = f;
        ss = fmaf(f, f, ss);
    }
    ss += __shfl_xor_sync(0xffffffffu, ss, 1);
    ss += __shfl_xor_sync(0xffffffffu, ss, 2);
    float inv2 = rsqrtf(ss + 1e-10f);

    if (J < NB) {
        float* dst = vbuf + J * VSTRIDE + g * 9;
        #pragma unroll
        for (int k = 0; k < 9; k++) dst[k] = v[k] * inv2;
    }
    __syncthreads();

    float* obase = out + (size_t)blockIdx.x * (NB * 36);
    #pragma unroll
    for (int e = tid; e < NB * 36; e += K2_THREADS) {
        int Jx = e / 36;
        int r  = e - Jx * 36;
        obase[e] = vbuf[Jx * VSTRIDE + r];
    }
}

// ---------------------------------------------------------------------------
extern "C" void kernel_launch(void* const* d_in, const int* in_sizes, int n_in,
                              void* d_out, int out_size)
{
    const float* x      = (const float*)d_in[0];
    const float* coeffs = (const float*)d_in[1];
    float* out          = (float*)d_out;

    float *hist, *cellss;
    cudaGetSymbolAddress((void**)&hist, g_hist);
    cudaGetSymbolAddress((void**)&cellss, g_cellss);

    dim3 g1(NR, B);
    hog_cells_kernel<<<g1, CROP>>>(x, coeffs, hist, cellss);

    hog_blocks_kernel<<<B * NB, K2_THREADS>>>(hist, cellss, out);
}

// round 12
// speedup vs baseline: 1.2505x; 1.0403x over previous
#include <cuda_runtime.h>
#include <cuda_bf16.h>
#include <math.h>

#define CROP 448
#define NR   56      // cells per side
#define NB   55      // blocks per side
#define B    48
#define IMG  512
#define TOP  32
#define QPR  112     // float4 quads per row (448/4)
#define SGW  456     // padded smem row width: col c at index c+4

// Cell histogram scratch: [b][cell_r][cell_c][bin]
__device__ float g_hist[(size_t)B * NR * NR * 9];
// Per-cell sum of squares: [b][cell_r][cell_c]
__device__ float g_cellss[(size_t)B * NR * NR];

__device__ __forceinline__ float fsqrt_approx(float x) {
    float r;
    asm("sqrt.approx.f32 %0, %1;" : "=f"(r) : "f"(x));
    return r;
}
__device__ __forceinline__ float frcp_approx(float x) {
    float r;
    asm("rcp.approx.f32 %0, %1;" : "=f"(r) : "f"(x));
    return r;
}

// ---------------------------------------------------------------------------
// Kernel 1: gray -> sqrt -> gradients -> per-cell prefix histograms (+cell ss)
// grid: (NR, B), block: 448 threads (one per crop column)
// Binning via cotangent comparison: w = u/|gr| vs cot(20k).
// vv = fabsf(gr) guarantees +0 so w = +inf (bin 0) for degenerate angles,
// matching the reference's 180 % 180 = 0 behavior.
// ---------------------------------------------------------------------------
__global__ __launch_bounds__(CROP) void hog_cells_kernel(
    const float* __restrict__ x, const float* __restrict__ coeffs,
    float* __restrict__ hist, float* __restrict__ cellss)
{
    __shared__ float sg[10][SGW];

    const int cr = blockIdx.x;       // cell row 0..55
    const int b  = blockIdx.y;
    const int c  = threadIdx.x;      // crop column 0..447
    const int r0 = cr * 8;

    const float c0 = coeffs[0], c1 = coeffs[1], c2 = coeffs[2];
    const float* base = x + (size_t)b * 3 * IMG * IMG;

    // Stage 10 rows of sqrt(gray); reflection clamp makes boundary gr = 0.
    // Edge-column reflections written inline by quad-0 / quad-111 threads.
    #pragma unroll
    for (int e = c; e < 10 * QPR; e += CROP) {
        int i = e / QPR;
        int q = e - i * QPR;
        int r = r0 - 1 + i;
        if (r < 0) r = -r;                        // -1 -> 1
        if (r > CROP - 1) r = 2 * (CROP - 1) - r; // 448 -> 446
        const float4* p = (const float4*)(base + (size_t)(r + TOP) * IMG + TOP) + q;
        float4 a0 = p[0];
        float4 a1 = p[(IMG * IMG) / 4];
        float4 a2 = p[(2 * IMG * IMG) / 4];
        float4 g;
        g.x = fsqrt_approx(fmaf(c0, a0.x, fmaf(c1, a1.x, c2 * a2.x)));
        g.y = fsqrt_approx(fmaf(c0, a0.y, fmaf(c1, a1.y, c2 * a2.y)));
        g.z = fsqrt_approx(fmaf(c0, a0.z, fmaf(c1, a1.z, c2 * a2.z)));
        g.w = fsqrt_approx(fmaf(c0, a0.w, fmaf(c1, a1.w, c2 * a2.w)));
        *((float4*)&sg[i][4 + q * 4]) = g;
        if (q == 0)       sg[i][3]   = g.y;   // col -1  := col 1
        if (q == QPR - 1) sg[i][452] = g.z;   // col 448 := col 446
    }
    __syncthreads();

    // cot(20k degrees), k = 1..8
    const float KT[8] = { 2.7474774f,  1.1917536f,  0.57735027f,  0.17632698f,
                         -0.17632698f, -0.57735027f, -1.1917536f, -2.7474774f};

    float vreg[10];
    #pragma unroll
    for (int i = 0; i < 10; i++) vreg[i] = sg[i][c + 4];

    // Prefix histogram: H[k] = sum of mag over pixels with angle >= 20k.
    float H[9];
    #pragma unroll
    for (int k = 0; k < 9; k++) H[k] = 0.f;

    #pragma unroll
    for (int i = 0; i < 8; i++) {
        float gr = vreg[i + 2] - vreg[i];
        float gc = sg[i + 1][c + 5] - sg[i + 1][c + 3];

        float mag = fsqrt_approx(fmaf(gr, gr, gc * gc));

        // Fold into upper half-plane: angle in [0,180). vv = |gr| (always +0
        // when gr is a signed zero -> w = +inf -> bin 0, matching 180%180=0).
        bool neg = (gr < 0.f) || (gr == 0.f && gc < 0.f);
        float u  = neg ? -gc : gc;
        float vv = fabsf(gr);

        // w = cot(angle); angle >= 20k  <=>  w <= cot(20k).
        float w = u * frcp_approx(vv);

        H[0] += mag;
        #pragma unroll
        for (int k = 0; k < 8; k++)
            if (w <= KT[k]) H[k + 1] += mag;
    }

    #pragma unroll
    for (int k = 0; k < 9; k++) {
        H[k] += __shfl_xor_sync(0xffffffffu, H[k], 1);
        H[k] += __shfl_xor_sync(0xffffffffu, H[k], 2);
        H[k] += __shfl_xor_sync(0xffffffffu, H[k], 4);
    }

    if ((c & 7) == 0) {
        int cell = c >> 3;
        size_t cidx = ((size_t)b * NR + cr) * NR + cell;
        float ss = 0.f;
        #pragma unroll
        for (int k = 0; k < 9; k++) {
            float hk = ((k < 8) ? (H[k] - H[k + 1]) : H[8]) * (1.0f / 64.0f);
            hist[cidx * 9 + k] = hk;
            ss += hk * hk;
        }
        cellss[cidx] = ss;
    }
}

// ---------------------------------------------------------------------------
// Kernel 2: L2-Hys block normalization. One CTA per (b, I) block-row.
// [R7 version verbatim — best measured 12.3us, frozen]
// ---------------------------------------------------------------------------
#define K2_THREADS 256
#define VSTRIDE 37          // padded per-block stride in vbuf (kills conflicts)

__global__ __launch_bounds__(K2_THREADS) void hog_blocks_kernel(
    const float* __restrict__ hist, const float* __restrict__ cellss,
    float* __restrict__ out)
{
    __shared__ float sh[2 * NR * 9];      // hist rows I, I+1 (1008)
    __shared__ float scs[2 * NR];         // cell ss rows I, I+1 (112)
    __shared__ float vbuf[NB * VSTRIDE];  // normalized blocks, padded stride

    const int b = blockIdx.x / NB;
    const int I = blockIdx.x % NB;
    const int tid = threadIdx.x;

    {
        const float4* src4 = (const float4*)(hist + ((size_t)b * NR + I) * NR * 9);
        if (tid < 252) ((float4*)sh)[tid] = src4[tid];
        const float* cs = cellss + ((size_t)b * NR + I) * NR;
        if (tid < 2 * NR) scs[tid] = cs[tid];
    }
    __syncthreads();

    const int w    = tid >> 5;
    const int lane = tid & 31;
    const int g    = lane & 3;            // cell within block
    const int J    = w + 8 * (lane >> 2); // block column (may be >= NB)
    const int Jc   = (J < NB) ? J : (NB - 1);  // clamped for safe reads

    float inv1 = rsqrtf(scs[Jc] + scs[Jc + 1] + scs[NR + Jc] + scs[NR + Jc + 1]
                        + 1e-10f);

    const float* cell = sh + (g >> 1) * (NR * 9) + (Jc + (g & 1)) * 9;
    float v[9];
    float ss = 0.f;
    #pragma unroll
    for (int k = 0; k < 9; k++) {
        float f = fminf(cell[k] * inv1, 0.2f);
        v[k] = f;
        ss = fmaf(f, f, ss);
    }
    ss += __shfl_xor_sync(0xffffffffu, ss, 1);
    ss += __shfl_xor_sync(0xffffffffu, ss, 2);
    float inv2 = rsqrtf(ss + 1e-10f);

    if (J < NB) {
        float* dst = vbuf + J * VSTRIDE + g * 9;
        #pragma unroll
        for (int k = 0; k < 9; k++) dst[k] = v[k] * inv2;
    }
    __syncthreads();

    float* obase = out + (size_t)blockIdx.x * (NB * 36);
    #pragma unroll
    for (int e = tid; e < NB * 36; e += K2_THREADS) {
        int Jx = e / 36;
        int r  = e - Jx * 36;
        obase[e] = vbuf[Jx * VSTRIDE + r];
    }
}

// ---------------------------------------------------------------------------
extern "C" void kernel_launch(void* const* d_in, const int* in_sizes, int n_in,
                              void* d_out, int out_size)
{
    const float* x      = (const float*)d_in[0];
    const float* coeffs = (const float*)d_in[1];
    float* out          = (float*)d_out;

    float *hist, *cellss;
    cudaGetSymbolAddress((void**)&hist, g_hist);
    cudaGetSymbolAddress((void**)&cellss, g_cellss);

    dim3 g1(NR, B);
    hog_cells_kernel<<<g1, CROP>>>(x, coeffs, hist, cellss);

    hog_blocks_kernel<<<B * NB, K2_THREADS>>>(hist, cellss, out);
}